// round 13
// baseline (speedup 1.0000x reference)
#include <cuda_runtime.h>

// Quan2d, round 10: R7 two-patches-per-thread base + layer-2 elimination.
//
// Layer 1 in tangent form (RY = c*[[1,-t],[t,1]]; uniform scalars cancel),
// CNOT ring as compile-time permutation. Layer 2 is removed entirely:
// RY gates on wires != w commute with Z_w, so
//   <Z_w> = [cos(th_w)*(2*S_w - n) - sin(th_w)*C_w] / n
// with S_w = sum_{bit_w=0} t^2, n = sum t^2, C_w = 2*sum_pairs t_lo*t_hi,
// th_w = full layer-2 angle w8[4+w].
// CNOT ring perm h: {0,13,3,14,6,11,5,8,12,1,15,2,10,7,9,4}.

__host__ __device__ constexpr int permIdx(int s) {
    int b0 = (s >> 3) & 1, b1 = (s >> 2) & 1, b2 = (s >> 1) & 1, b3 = s & 1;
    int h0 = b0 ^ b3, h1 = b0 ^ b1 ^ b3, h2 = b1 ^ b2, h3 = b2 ^ b3;
    return (h0 << 3) | (h1 << 2) | (h2 << 1) | h3;
}

__device__ __forceinline__ float frcp_approx(float v) {
    float r; asm("rcp.approx.f32 %0, %1;" : "=f"(r) : "f"(v)); return r;
}

// Layer 1 + perm + reduction + layer-2-free expectation for one patch.
__device__ __forceinline__ float4 run_patch(const float (&ap)[16],
                                            const float* __restrict__ ct,
                                            const float* __restrict__ cs,
                                            const float* __restrict__ sn) {
    float a[16];
    #pragma unroll
    for (int s = 0; s < 16; s++) a[s] = ap[s];

    // RY layer 1 (tangent form): gate g acts on bit (8 >> g)
    #pragma unroll
    for (int g = 0; g < 4; g++) {
        const float tg = ct[g];
        const int BIT = 8 >> g;
        #pragma unroll
        for (int lo = 0; lo < 16; lo++) {
            if (lo & BIT) continue;
            const float xx = a[lo], yy = a[lo | BIT];
            a[lo]       = fmaf(-tg, yy, xx);
            a[lo | BIT] = fmaf( tg, xx, yy);
        }
    }

    // CNOT ring permutation (register renaming)
    float t[16];
    #pragma unroll
    for (int s = 0; s < 16; s++) t[s] = a[permIdx(s)];

    // squares fused into first tree level
    float qe[8], s1[8];
    #pragma unroll
    for (int k = 0; k < 8; k++) {
        qe[k] = t[2 * k] * t[2 * k];
        s1[k] = fmaf(t[2 * k + 1], t[2 * k + 1], qe[k]);
    }
    float s2[4];
    #pragma unroll
    for (int k = 0; k < 4; k++) s2[k] = s1[2 * k] + s1[2 * k + 1];
    const float s3a = s2[0] + s2[1];
    const float s3b = s2[2] + s2[3];
    const float n   = s3a + s3b;

    const float S0 = s3a;                                  // wire0: bit3==0
    const float S1 = s2[0] + s2[2];                        // wire1: bit2==0
    const float S2 = (s1[0] + s1[2]) + (s1[4] + s1[6]);    // wire2: bit1==0
    const float S3 = ((qe[0] + qe[1]) + (qe[2] + qe[3]))   // wire3: bit0==0
                   + ((qe[4] + qe[5]) + (qe[6] + qe[7]));

    // D_w = 2*S_w - n
    const float D0 = fmaf(S0, 2.0f, -n);
    const float D1 = fmaf(S1, 2.0f, -n);
    const float D2 = fmaf(S2, 2.0f, -n);
    const float D3 = fmaf(S3, 2.0f, -n);

    // C_w = 2 * sum over bit-w pairs of t_lo * t_hi
    float C0 = t[0] * t[8];
    #pragma unroll
    for (int s = 1; s < 8; s++) C0 = fmaf(t[s], t[s | 8], C0);

    float C1 = t[0] * t[4];
    #pragma unroll
    for (int j = 1; j < 8; j++) {
        const int s = (j & 3) | ((j >> 2) << 3);           // {0..3, 8..11}
        C1 = fmaf(t[s], t[s | 4], C1);
    }

    float C2 = t[0] * t[2];
    #pragma unroll
    for (int j = 1; j < 8; j++) {
        const int s = (j & 1) | (((j >> 1) & 3) << 2);     // {0,1,4,5,8,9,12,13}
        C2 = fmaf(t[s], t[s | 2], C2);
    }

    float C3 = t[0] * t[1];
    #pragma unroll
    for (int j = 1; j < 8; j++) C3 = fmaf(t[2 * j], t[2 * j + 1], C3);

    C0 += C0; C1 += C1; C2 += C2; C3 += C3;

    // e_w = cos(th_w)*D_w - sin(th_w)*C_w ; out = e_w / n
    const float rn = frcp_approx(n);
    float4 o;
    o.x = fmaf(cs[0], D0, -sn[0] * C0) * rn;
    o.y = fmaf(cs[1], D1, -sn[1] * C1) * rn;
    o.z = fmaf(cs[2], D2, -sn[2] * C2) * rn;
    o.w = fmaf(cs[3], D3, -sn[3] * C3) * rn;
    return o;
}

__global__ __launch_bounds__(256)
void quan2d_kernel(const float* __restrict__ x,
                   const float* __restrict__ w8,
                   float* __restrict__ out)
{
    __shared__ float sh[12];   // [0:4) tan(w/2) L1, [4:8) cos(th) L2, [8:12) sin(th) L2
    const int tid = threadIdx.x;
    if (tid < 4) {
        sh[tid] = __tanf(0.5f * w8[tid]);
        float sv, cv;
        __sincosf(w8[4 + tid], &sv, &cv);
        sh[4 + tid] = cv;
        sh[8 + tid] = sv;
    }
    __syncthreads();

    float ct[4], cs[4], sn[4];
    #pragma unroll
    for (int i = 0; i < 4; i++) { ct[i] = sh[i]; cs[i] = sh[4 + i]; sn[i] = sh[8 + i]; }

    const int b  = blockIdx.x * 2 + (tid >> 7);   // image
    const int t7 = tid & 127;
    const int pr = t7 >> 3;                        // patch row 0..15
    const int k  = t7 & 7;                         // pair idx; patches pc=2k,2k+1
    const float* img = x + (size_t)b * 1024;

    // --- load rows 2pr..2pr+3, cols 4k..4k+5 (zero-pad bottom/right) ---
    const bool pA = (pr < 15);
    const bool pB = (k < 7);
    float a0[16], a1[16];
    #pragma unroll
    for (int i = 0; i < 4; i++) {
        const float* base = img + (2 * pr + i) * 32 + 4 * k;
        const bool rok = (i < 2) || pA;
        float4 F = rok ? __ldg((const float4*)base)
                       : make_float4(0.f, 0.f, 0.f, 0.f);
        float2 G = (rok && pB) ? __ldg((const float2*)(base + 4))
                               : make_float2(0.f, 0.f);
        a0[4 * i + 0] = F.x; a0[4 * i + 1] = F.y;
        a0[4 * i + 2] = F.z; a0[4 * i + 3] = F.w;
        a1[4 * i + 0] = F.z; a1[4 * i + 1] = F.w;
        a1[4 * i + 2] = G.x; a1[4 * i + 3] = G.y;
    }

    const float4 o0 = run_patch(a0, ct, cs, sn);
    const float4 o1 = run_patch(a1, ct, cs, sn);

    float4* op = (float4*)out + (size_t)b * 256 + pr * 16 + 2 * k;
    op[0] = o0;
    op[1] = o1;
}

extern "C" void kernel_launch(void* const* d_in, const int* in_sizes, int n_in,
                              void* d_out, int out_size)
{
    const float* x = (const float*)d_in[0];   // [B,1,32,32] fp32
    const float* w = (const float*)d_in[1];   // [1,8] fp32
    const int B = in_sizes[0] / 1024;
    quan2d_kernel<<<B / 2, 256>>>(x, w, (float*)d_out);
}

// round 14
// speedup vs baseline: 1.3689x; 1.3689x over previous
#include <cuda_runtime.h>

// Quan2d, round 14: R7 two-patches-per-thread base + shared row-transform.
//
// Layer-1 RY gates on wires 0,1 act only on the patch-row index; the two
// horizontal patches (pc=2k, 2k+1) share all image columns, so those two
// gates are applied ONCE to the 4x6 pixel tile (48 fma) instead of per
// patch (64). Per patch: layer-1 col gates (wires 2,3), CNOT perm, full
// layer 2, fused square+tree reduction. All gates tangent-form
// (RY = c*[[1,-t],[t,1]]; uniform scalars cancel in <Z_w> = 2*S_w/n - 1).
// CNOT ring perm h: {0,13,3,14,6,11,5,8,12,1,15,2,10,7,9,4}.

__host__ __device__ constexpr int permIdx(int s) {
    int b0 = (s >> 3) & 1, b1 = (s >> 2) & 1, b2 = (s >> 1) & 1, b3 = s & 1;
    int h0 = b0 ^ b3, h1 = b0 ^ b1 ^ b3, h2 = b1 ^ b2, h3 = b2 ^ b3;
    return (h0 << 3) | (h1 << 2) | (h2 << 1) | h3;
}

__device__ __forceinline__ float frcp_approx(float v) {
    float r; asm("rcp.approx.f32 %0, %1;" : "=f"(r) : "f"(v)); return r;
}

// Input: a[16] already row-transformed (wires 0,1 of layer 1 applied).
// Applies layer-1 col gates (wires 2,3), CNOT perm, layer 2, reduction.
__device__ __forceinline__ float4 run_patch(float (&a)[16],
                                            const float* __restrict__ ct) {
    // layer-1 col gates: wire 2 -> bit 2(value 2), wire 3 -> bit 1(value 1)
    #pragma unroll
    for (int g = 2; g < 4; g++) {
        const float tg = ct[g];
        const int BIT = 8 >> g;
        #pragma unroll
        for (int lo = 0; lo < 16; lo++) {
            if (lo & BIT) continue;
            const float xx = a[lo], yy = a[lo | BIT];
            a[lo]       = fmaf(-tg, yy, xx);
            a[lo | BIT] = fmaf( tg, xx, yy);
        }
    }

    // CNOT ring permutation (register renaming)
    float t[16];
    #pragma unroll
    for (int s = 0; s < 16; s++) t[s] = a[permIdx(s)];

    // layer 2 (all four wires)
    #pragma unroll
    for (int g = 0; g < 4; g++) {
        const float tg = ct[4 + g];
        const int BIT = 8 >> g;
        #pragma unroll
        for (int lo = 0; lo < 16; lo++) {
            if (lo & BIT) continue;
            const float xx = t[lo], yy = t[lo | BIT];
            t[lo]       = fmaf(-tg, yy, xx);
            t[lo | BIT] = fmaf( tg, xx, yy);
        }
    }

    // fused squares + tree reduction
    float qe[8], s1[8];
    #pragma unroll
    for (int k = 0; k < 8; k++) {
        qe[k] = t[2 * k] * t[2 * k];
        s1[k] = fmaf(t[2 * k + 1], t[2 * k + 1], qe[k]);
    }
    float s2[4];
    #pragma unroll
    for (int k = 0; k < 4; k++) s2[k] = s1[2 * k] + s1[2 * k + 1];
    const float s3a = s2[0] + s2[1];
    const float s3b = s2[2] + s2[3];
    const float n   = s3a + s3b;

    const float S0 = s3a;                                  // wire0: bit3==0
    const float S1 = s2[0] + s2[2];                        // wire1: bit2==0
    const float S2 = (s1[0] + s1[2]) + (s1[4] + s1[6]);    // wire2: bit1==0
    const float S3 = ((qe[0] + qe[1]) + (qe[2] + qe[3]))   // wire3: bit0==0
                   + ((qe[4] + qe[5]) + (qe[6] + qe[7]));

    const float r2 = 2.0f * frcp_approx(n);
    return make_float4(fmaf(S0, r2, -1.0f), fmaf(S1, r2, -1.0f),
                       fmaf(S2, r2, -1.0f), fmaf(S3, r2, -1.0f));
}

__global__ __launch_bounds__(256)
void quan2d_kernel(const float* __restrict__ x,
                   const float* __restrict__ w8,
                   float* __restrict__ out)
{
    __shared__ float cts[8];
    const int tid = threadIdx.x;
    if (tid < 8) cts[tid] = __tanf(0.5f * w8[tid]);
    __syncthreads();

    float ct[8];
    #pragma unroll
    for (int i = 0; i < 8; i++) ct[i] = cts[i];

    const int b  = blockIdx.x * 2 + (tid >> 7);   // image
    const int t7 = tid & 127;
    const int pr = t7 >> 3;                        // patch row 0..15
    const int k  = t7 & 7;                         // pair idx; patches pc=2k,2k+1
    const float* img = x + (size_t)b * 1024;

    // --- load 4x6 tile: rows 2pr..2pr+3, cols 4k..4k+5 (zero-pad b/r) ---
    const bool pA = (pr < 15);
    const bool pB = (k < 7);
    float T[24];   // T[6*r + c]
    #pragma unroll
    for (int i = 0; i < 4; i++) {
        const float* base = img + (2 * pr + i) * 32 + 4 * k;
        const bool rok = (i < 2) || pA;
        float4 F = rok ? __ldg((const float4*)base)
                       : make_float4(0.f, 0.f, 0.f, 0.f);
        float2 G = (rok && pB) ? __ldg((const float2*)(base + 4))
                               : make_float2(0.f, 0.f);
        T[6 * i + 0] = F.x; T[6 * i + 1] = F.y;
        T[6 * i + 2] = F.z; T[6 * i + 3] = F.w;
        T[6 * i + 4] = G.x; T[6 * i + 5] = G.y;
    }

    // --- shared layer-1 row gates (wires 0,1) on all 6 tile columns ---
    {
        const float t0 = ct[0], t1 = ct[1];
        #pragma unroll
        for (int c = 0; c < 6; c++) {
            const float x0 = T[c], x1 = T[6 + c], x2 = T[12 + c], x3 = T[18 + c];
            // wire 0 (bit3): pairs (row0,row2),(row1,row3)
            const float y0 = fmaf(-t0, x2, x0);
            const float y2 = fmaf( t0, x0, x2);
            const float y1 = fmaf(-t0, x3, x1);
            const float y3 = fmaf( t0, x1, x3);
            // wire 1 (bit2): pairs (row0,row1),(row2,row3)
            T[c]      = fmaf(-t1, y1, y0);
            T[6 + c]  = fmaf( t1, y0, y1);
            T[12 + c] = fmaf(-t1, y3, y2);
            T[18 + c] = fmaf( t1, y2, y3);
        }
    }

    float4* op = (float4*)out + (size_t)b * 256 + pr * 16 + 2 * k;

    // --- patch 0: tile cols 0..3 ---
    {
        float a[16];
        #pragma unroll
        for (int r = 0; r < 4; r++)
            #pragma unroll
            for (int c = 0; c < 4; c++)
                a[4 * r + c] = T[6 * r + c];
        op[0] = run_patch(a, ct);
    }
    // --- patch 1: tile cols 2..5 ---
    {
        float a[16];
        #pragma unroll
        for (int r = 0; r < 4; r++)
            #pragma unroll
            for (int c = 0; c < 4; c++)
                a[4 * r + c] = T[6 * r + 2 + c];
        op[1] = run_patch(a, ct);
    }
}

extern "C" void kernel_launch(void* const* d_in, const int* in_sizes, int n_in,
                              void* d_out, int out_size)
{
    const float* x = (const float*)d_in[0];   // [B,1,32,32] fp32
    const float* w = (const float*)d_in[1];   // [1,8] fp32
    const int B = in_sizes[0] / 1024;
    quan2d_kernel<<<B / 2, 256>>>(x, w, (float*)d_out);
}